// round 2
// baseline (speedup 1.0000x reference)
#include <cuda_runtime.h>

// Problem constants (VectorQuantizer_317827580710)
#define NB   32      // batch
#define D    256     // embedding dim
#define HW   1024    // 32*32 spatial
#define N    32768   // NB*HW rows
#define K    1024    // num embeddings
#define QELEMS (N * D)   // 8388608 quantized elements
#define NPART  (QELEMS / 256)  // 32768 loss partials

// GEMM tile config
#define BM 64
#define BN 128
#define BNP (BN + 4)
#define BK 16
#define TM 4
#define TN 8

// Scratch (no device allocation allowed)
__device__ float g_wnorm[K];
__device__ float g_xnorm[N];
__device__ int   g_idx[N];
__device__ int   g_hist[K];
__device__ float g_partial[NPART];

__device__ __forceinline__ float block_reduce_f(float v, float* s) {
    int tid = threadIdx.x;
#pragma unroll
    for (int o = 16; o; o >>= 1) v += __shfl_down_sync(0xffffffffu, v, o);
    if ((tid & 31) == 0) s[tid >> 5] = v;
    __syncthreads();
    if (tid < 32) {
        v = (tid < 8) ? s[tid] : 0.f;
#pragma unroll
        for (int o = 4; o; o >>= 1) v += __shfl_down_sync(0xffffffffu, v, o);
    }
    return v;  // valid in tid 0
}

// ---------------------------------------------------------------------------
// Kernel 0a: codebook squared norms (fp64 -> correctly rounded fp32) + hist zero.
__global__ __launch_bounds__(256) void k_wnorm(const float* __restrict__ w) {
    __shared__ double sd[8];
    int c = blockIdx.x;
    int tid = threadIdx.x;
    float v = w[c * D + tid];
    double s = (double)v * (double)v;
#pragma unroll
    for (int o = 16; o; o >>= 1) s += __shfl_down_sync(0xffffffffu, s, o);
    if ((tid & 31) == 0) sd[tid >> 5] = s;
    __syncthreads();
    if (tid == 0) {
        double t = 0.0;
        for (int i = 0; i < 8; i++) t += sd[i];
        g_wnorm[c] = (float)t;
        g_hist[c] = 0;
    }
}

// Kernel 0b: per-row ||x||^2 (fp64 -> fp32). grid = N/32, block (32,8).
// x[b, d, hw]: 32 consecutive hw per block -> coalesced over tx.
__global__ __launch_bounds__(256) void k_xnorm(const float* __restrict__ x) {
    __shared__ double part[8][32];
    int tx = threadIdx.x;   // hw lane 0..31
    int ty = threadIdx.y;   // d group 0..7
    int n0 = blockIdx.x * 32;
    int b  = n0 >> 10;
    int hw = (n0 & (HW - 1)) + tx;
    const float* xb = x + b * (D * HW) + hw;
    double s = 0.0;
    for (int d = ty; d < D; d += 8) {
        float v = xb[d * HW];
        s += (double)v * (double)v;
    }
    part[ty][tx] = s;
    __syncthreads();
    if (ty == 0) {
        double t = 0.0;
#pragma unroll
        for (int i = 0; i < 8; i++) t += part[i][tx];
        g_xnorm[n0 + tx] = (float)t;
    }
}

// ---------------------------------------------------------------------------
// Kernel 1: fused distance GEMM + argmin, replicating reference arithmetic:
//   dot  = fp32 single-accumulator FMA, k ascending (matches Eigen / cutlass)
//   dist = fl( fl(xn2 + wn2) - 2*dot )   (2*dot exact; FMA-contraction identical)
//   argmin: first index on exact float ties.
__global__ __launch_bounds__(256) void k_argmin(const float* __restrict__ x,
                                                const float* __restrict__ w) {
    __shared__ __align__(16) float As[BK][BM];
    __shared__ __align__(16) float Bs[BK][BNP];
    __shared__ __align__(16) float Wn[BN];
    __shared__ __align__(16) float Xs[BM];
    __shared__ float Rv[BM][16];
    __shared__ int   Ri[BM][16];

    const int tid = threadIdx.x;
    const int tx = tid & 15, ty = tid >> 4;
    const int n0 = blockIdx.x * BM;
    const float* xb = x + (n0 >> 10) * (D * HW) + (n0 & (HW - 1));

    const int lm4 = tid & 15, lk = tid >> 4;        // As load coords
    const int bc  = tid >> 2, bq = (tid & 3) * 4;   // Bs load coords

    if (tid < BM / 4)
        *(float4*)(Xs + tid * 4) = *(const float4*)(g_xnorm + n0 + tid * 4);

    float bestv[TM];
    int   besti[TM];
#pragma unroll
    for (int i = 0; i < TM; i++) { bestv[i] = 3.4e38f; besti[i] = 0; }

    for (int ct = 0; ct < K / BN; ct++) {
        if (tid < BN / 4)
            *(float4*)(Wn + tid * 4) = *(const float4*)(g_wnorm + ct * BN + tid * 4);

        float acc[TM][TN];
#pragma unroll
        for (int i = 0; i < TM; i++)
#pragma unroll
            for (int j = 0; j < TN; j++) acc[i][j] = 0.f;

        const float* wt = w + (ct * BN) * D;

        for (int dt = 0; dt < D / BK; dt++) {
            *(float4*)(&As[lk][lm4 * 4]) =
                *(const float4*)(xb + (dt * BK + lk) * HW + lm4 * 4);
#pragma unroll
            for (int it = 0; it < 2; it++) {
                int c = bc + it * 64;
                float4 t = *(const float4*)(wt + c * D + dt * BK + bq);
                Bs[bq + 0][c] = t.x;
                Bs[bq + 1][c] = t.y;
                Bs[bq + 2][c] = t.z;
                Bs[bq + 3][c] = t.w;
            }
            __syncthreads();
#pragma unroll
            for (int kk = 0; kk < BK; kk++) {   // k strictly ascending globally
                float4 a  = *(const float4*)(&As[kk][ty * TM]);
                float4 b0 = *(const float4*)(&Bs[kk][tx * TN]);
                float4 b1 = *(const float4*)(&Bs[kk][tx * TN + 4]);
                float av[TM] = {a.x, a.y, a.z, a.w};
                float bv[TN] = {b0.x, b0.y, b0.z, b0.w, b1.x, b1.y, b1.z, b1.w};
#pragma unroll
                for (int i = 0; i < TM; i++)
#pragma unroll
                    for (int j = 0; j < TN; j++)
                        acc[i][j] = fmaf(av[i], bv[j], acc[i][j]);
            }
            __syncthreads();
        }
        // fold with reference-identical rounding: (xn2 + wn2) - 2*dot
#pragma unroll
        for (int i = 0; i < TM; i++) {
            float xs = Xs[ty * TM + i];
#pragma unroll
            for (int j = 0; j < TN; j++) {
                float t1 = xs + Wn[tx * TN + j];
                float dist = t1 - 2.f * acc[i][j];
                if (dist < bestv[i]) { bestv[i] = dist; besti[i] = ct * BN + tx * TN + j; }
            }
        }
        __syncthreads();  // protect Wn/smem reuse across ct iterations
    }

#pragma unroll
    for (int i = 0; i < TM; i++) {
        Rv[ty * TM + i][tx] = bestv[i];
        Ri[ty * TM + i][tx] = besti[i];
    }
    __syncthreads();
    if (tid < BM) {
        float bv = Rv[tid][0];
        int   bi = Ri[tid][0];
#pragma unroll
        for (int t = 1; t < 16; t++) {
            float v = Rv[tid][t];
            int  ix = Ri[tid][t];
            if (v < bv || (v == bv && ix < bi)) { bv = v; bi = ix; }
        }
        g_idx[n0 + tid] = bi;
    }
}

// ---------------------------------------------------------------------------
// Kernel 2: quantized_st = x + (q - x) in [B,C,H,W] layout + loss partials.
__global__ __launch_bounds__(256) void k_quant(const float* __restrict__ x,
                                               const float* __restrict__ w,
                                               float* __restrict__ outq) {
    __shared__ float s[8];
    int gid = blockIdx.x * 256 + threadIdx.x;
    int hw = gid & (HW - 1);
    int d  = (gid >> 10) & (D - 1);
    int b  = gid >> 18;
    int idx = __ldg(&g_idx[(b << 10) + hw]);
    float xv = x[gid];
    float qv = __ldg(&w[idx * D + d]);
    float df = qv - xv;
    outq[gid] = xv + df;  // straight-through value
    float v = block_reduce_f(df * df, s);
    if (threadIdx.x == 0) g_partial[blockIdx.x] = v;
}

// ---------------------------------------------------------------------------
// Kernel 3: one-hot encodings (float2; base 8B aligned) + exact int histogram.
__global__ __launch_bounds__(256) void k_enc(float2* __restrict__ enc) {
    unsigned gid = blockIdx.x * 256u + threadIdx.x;  // < N*K/2
    int n  = gid >> 9;
    int c2 = gid & 511;
    int idx = __ldg(&g_idx[n]);
    float2 v = make_float2(0.f, 0.f);
    if ((idx >> 1) == c2) {
        if (idx & 1) v.y = 1.f; else v.x = 1.f;
        atomicAdd(&g_hist[idx], 1);
    }
    enc[gid] = v;
}

// ---------------------------------------------------------------------------
// Kernel 4: finalize loss + perplexity (deterministic double reductions).
__global__ __launch_bounds__(256) void k_final(float* __restrict__ out) {
    __shared__ double sd[8];
    int tid = threadIdx.x;

    double s = 0.0;
    for (int i = tid; i < NPART; i += 256) s += (double)g_partial[i];
#pragma unroll
    for (int o = 16; o; o >>= 1) s += __shfl_down_sync(0xffffffffu, s, o);
    if ((tid & 31) == 0) sd[tid >> 5] = s;
    __syncthreads();
    if (tid == 0) {
        double t = 0.0;
        for (int i = 0; i < 8; i++) t += sd[i];
        out[0] = (float)(t / (double)QELEMS * 1.25);
    }
    __syncthreads();

    double e = 0.0;
    for (int i = tid; i < K; i += 256) {
        double p = (double)g_hist[i] / (double)N;
        e += p * log(p + 1e-10);
    }
#pragma unroll
    for (int o = 16; o; o >>= 1) e += __shfl_down_sync(0xffffffffu, e, o);
    if ((tid & 31) == 0) sd[tid >> 5] = e;
    __syncthreads();
    if (tid == 0) {
        double t = 0.0;
        for (int i = 0; i < 8; i++) t += sd[i];
        out[1 + QELEMS] = (float)exp(-t);
    }
}

// ---------------------------------------------------------------------------
extern "C" void kernel_launch(void* const* d_in, const int* in_sizes, int n_in,
                              void* d_out, int out_size) {
    const float* x = (const float*)d_in[0];   // inputs [32,256,32,32]
    const float* w = (const float*)d_in[1];   // weight [1024,256]
    float* out = (float*)d_out;
    // Output layout: [0]=loss, [1 .. 1+QELEMS)=quantized_st,
    //                [1+QELEMS]=perplexity, [2+QELEMS .. )=encodings
    k_wnorm <<<K, 256>>>(w);
    k_xnorm <<<N / 32, dim3(32, 8)>>>(x);
    k_argmin<<<N / BM, 256>>>(x, w);
    k_quant <<<QELEMS / 256, 256>>>(x, w, out + 1);
    k_enc   <<<(N * (K / 2)) / 256, 256>>>((float2*)(out + 2 + QELEMS));
    k_final <<<1, 256>>>(out);
}

// round 3
// speedup vs baseline: 1.5222x; 1.5222x over previous
#include <cuda_runtime.h>

// Problem constants (VectorQuantizer_317827580710)
#define NB   32
#define D    256
#define HW   1024
#define N    32768
#define K    1024
#define QELEMS (N * D)
#define NPART  1024          // k_quant grid size

// GEMM tile config
#define BM 128
#define BN 128
#define BNP 132
#define BK 16

// Scratch (no device allocation allowed)
__device__ float g_wnorm[K];
__device__ float g_xnorm[N];
__device__ int   g_idx[N];
__device__ int   g_hist[K];
__device__ float g_partial[NPART];

// ---- packed f32x2 helpers (per-component IEEE fp32 .rn — bit-identical to fmaf)
__device__ __forceinline__ unsigned long long f2dup(float a) {
    unsigned long long r; unsigned u = __float_as_uint(a);
    asm("mov.b64 %0, {%1, %1};" : "=l"(r) : "r"(u));
    return r;
}
__device__ __forceinline__ void ffma2(unsigned long long& d,
                                      unsigned long long a, unsigned long long b) {
    asm("fma.rn.f32x2 %0, %1, %2, %0;" : "+l"(d) : "l"(a), "l"(b));
}
__device__ __forceinline__ void unpk(unsigned long long v, float& lo, float& hi) {
    unsigned a, b;
    asm("mov.b64 {%0, %1}, %2;" : "=r"(a), "=r"(b) : "l"(v));
    lo = __uint_as_float(a); hi = __uint_as_float(b);
}
__device__ __forceinline__ void cpa16(unsigned dst, const void* src) {
    asm volatile("cp.async.ca.shared.global [%0], [%1], 16;" :: "r"(dst), "l"(src));
}

__device__ __forceinline__ float block_reduce_f(float v, float* s) {
    int tid = threadIdx.x;
#pragma unroll
    for (int o = 16; o; o >>= 1) v += __shfl_down_sync(0xffffffffu, v, o);
    if ((tid & 31) == 0) s[tid >> 5] = v;
    __syncthreads();
    if (tid < 32) {
        v = (tid < 8) ? s[tid] : 0.f;
#pragma unroll
        for (int o = 4; o; o >>= 1) v += __shfl_down_sync(0xffffffffu, v, o);
    }
    return v;  // valid in tid 0
}

// ---------------------------------------------------------------------------
// Kernel 0a: codebook squared norms (fp64 -> correctly rounded fp32) + hist zero.
__global__ __launch_bounds__(256) void k_wnorm(const float* __restrict__ w) {
    __shared__ double sd[8];
    int c = blockIdx.x;
    int tid = threadIdx.x;
    float v = w[c * D + tid];
    double s = (double)v * (double)v;
#pragma unroll
    for (int o = 16; o; o >>= 1) s += __shfl_down_sync(0xffffffffu, s, o);
    if ((tid & 31) == 0) sd[tid >> 5] = s;
    __syncthreads();
    if (tid == 0) {
        double t = 0.0;
        for (int i = 0; i < 8; i++) t += sd[i];
        g_wnorm[c] = (float)t;
        g_hist[c] = 0;
    }
}

// Kernel 0b: per-row ||x||^2 (fp64 -> fp32). grid = N/32, block (32,8).
__global__ __launch_bounds__(256) void k_xnorm(const float* __restrict__ x) {
    __shared__ double part[8][32];
    int tx = threadIdx.x, ty = threadIdx.y;
    int n0 = blockIdx.x * 32;
    int b  = n0 >> 10;
    int hw = (n0 & (HW - 1)) + tx;
    const float* xb = x + b * (D * HW) + hw;
    double s = 0.0;
    for (int d = ty; d < D; d += 8) {
        float v = xb[d * HW];
        s += (double)v * (double)v;
    }
    part[ty][tx] = s;
    __syncthreads();
    if (ty == 0) {
        double t = 0.0;
#pragma unroll
        for (int i = 0; i < 8; i++) t += part[i][tx];
        g_xnorm[n0 + tx] = (float)t;
    }
}

// ---------------------------------------------------------------------------
// Kernel 1: fused distance GEMM + argmin using packed fma.rn.f32x2.
// Reference-identical arithmetic per column:
//   dot  = single fp32 accumulator, k strictly ascending, FMA
//   dist = fl( fl(xn2 + wn2) - 2*dot )     (2*dot exact)
//   argmin: first index on exact float ties.
__global__ __launch_bounds__(256) void k_argmin(const float* __restrict__ x,
                                                const float* __restrict__ w) {
    __shared__ __align__(16) union SM {
        struct { float As[2][BK][BM]; float Bs[2][BK][BNP]; } t;
        struct { float Rv[BM][16]; int Ri[BM][16]; } r;
    } sm;

    const int tid = threadIdx.x;
    const int tx = tid & 15, ty = tid >> 4;
    const int n0 = blockIdx.x * BM;
    const float* xb = x + (n0 >> 10) * (D * HW) + (n0 & (HW - 1));
    const int lk = tid >> 5, la4 = (tid & 31) * 4;   // A cp.async coords
    const int bc = tid >> 1, bq = (tid & 1) * 8;     // B load coords

    unsigned long long acc[8][4];
    float bestv[8]; int besti[8]; float xs[8];
#pragma unroll
    for (int i = 0; i < 8; i++) {
        bestv[i] = 3.4e38f; besti[i] = 0;
        xs[i] = g_xnorm[n0 + ty * 8 + i];
#pragma unroll
        for (int jp = 0; jp < 4; jp++) acc[i][jp] = 0ULL;
    }

    const unsigned asb = (unsigned)__cvta_generic_to_shared(&sm.t.As[0][0][0]);

    // prologue: tile (ct=0, dt=0) -> buffer 0
    {
        const float* s0 = xb + lk * HW + la4;
        cpa16(asb + (lk * BM + la4) * 4, s0);
        cpa16(asb + ((lk + 8) * BM + la4) * 4, s0 + 8 * HW);
        const float* p = w + bc * D + bq;
        float4 B0 = *(const float4*)p;
        float4 B1 = *(const float4*)(p + 4);
        asm volatile("cp.async.commit_group;");
        asm volatile("cp.async.wait_group 0;" ::: "memory");
        float* bsp = &sm.t.Bs[0][0][0];
        bsp[(bq + 0) * BNP + bc] = B0.x; bsp[(bq + 1) * BNP + bc] = B0.y;
        bsp[(bq + 2) * BNP + bc] = B0.z; bsp[(bq + 3) * BNP + bc] = B0.w;
        bsp[(bq + 4) * BNP + bc] = B1.x; bsp[(bq + 5) * BNP + bc] = B1.y;
        bsp[(bq + 6) * BNP + bc] = B1.z; bsp[(bq + 7) * BNP + bc] = B1.w;
        __syncthreads();
    }

    for (int it = 0; it < 128; ++it) {
        const int cur = it & 1, nxt = cur ^ 1;
        const bool more = (it + 1 < 128);
        float4 B0, B1;
        if (more) {
            const int i2 = it + 1, dt = i2 & 15, ct = i2 >> 4;
            const float* s0 = xb + (dt * BK + lk) * HW + la4;
            cpa16(asb + ((nxt * BK + lk) * BM + la4) * 4, s0);
            cpa16(asb + ((nxt * BK + lk + 8) * BM + la4) * 4, s0 + 8 * HW);
            const float* p = w + (ct * BN + bc) * D + dt * BK + bq;
            B0 = *(const float4*)p;
            B1 = *(const float4*)(p + 4);
            asm volatile("cp.async.commit_group;");
        }
        // compute on buffer cur (k ascending: dt outer, kk inner)
#pragma unroll
        for (int kk = 0; kk < BK; ++kk) {
            const float* ar = &sm.t.As[cur][kk][ty * 8];
            float4 a0 = *(const float4*)ar;
            float4 a1 = *(const float4*)(ar + 4);
            const ulonglong2* bp = (const ulonglong2*)&sm.t.Bs[cur][kk][tx * 8];
            ulonglong2 q0 = bp[0], q1 = bp[1];
            unsigned long long bb0 = q0.x, bb1 = q0.y, bb2 = q1.x, bb3 = q1.y;
            float av[8] = {a0.x, a0.y, a0.z, a0.w, a1.x, a1.y, a1.z, a1.w};
#pragma unroll
            for (int i = 0; i < 8; ++i) {
                unsigned long long ap = f2dup(av[i]);
                ffma2(acc[i][0], ap, bb0);
                ffma2(acc[i][1], ap, bb1);
                ffma2(acc[i][2], ap, bb2);
                ffma2(acc[i][3], ap, bb3);
            }
        }
        // fold at end of each ct block (cols ascending; strict < keeps first)
        if ((it & 15) == 15) {
            const int ct = it >> 4;
#pragma unroll
            for (int i = 0; i < 8; ++i) {
                const float xsv = xs[i];
#pragma unroll
                for (int jp = 0; jp < 4; ++jp) {
                    float lo, hi; unpk(acc[i][jp], lo, hi);
                    acc[i][jp] = 0ULL;
                    const int c0 = ct * BN + tx * 8 + jp * 2;
                    const float d0 = (xsv + __ldg(&g_wnorm[c0]))     - 2.f * lo;
                    const float d1 = (xsv + __ldg(&g_wnorm[c0 + 1])) - 2.f * hi;
                    if (d0 < bestv[i]) { bestv[i] = d0; besti[i] = c0; }
                    if (d1 < bestv[i]) { bestv[i] = d1; besti[i] = c0 + 1; }
                }
            }
        }
        if (more) {
            asm volatile("cp.async.wait_group 0;" ::: "memory");
            float* bsp = &sm.t.Bs[nxt][0][0];
            bsp[(bq + 0) * BNP + bc] = B0.x; bsp[(bq + 1) * BNP + bc] = B0.y;
            bsp[(bq + 2) * BNP + bc] = B0.z; bsp[(bq + 3) * BNP + bc] = B0.w;
            bsp[(bq + 4) * BNP + bc] = B1.x; bsp[(bq + 5) * BNP + bc] = B1.y;
            bsp[(bq + 6) * BNP + bc] = B1.z; bsp[(bq + 7) * BNP + bc] = B1.w;
            __syncthreads();
        }
    }

    __syncthreads();   // retire tile smem before union reuse
#pragma unroll
    for (int i = 0; i < 8; ++i) {
        sm.r.Rv[ty * 8 + i][tx] = bestv[i];
        sm.r.Ri[ty * 8 + i][tx] = besti[i];
    }
    __syncthreads();
    if (tid < BM) {
        float bv = sm.r.Rv[tid][0];
        int   bi = sm.r.Ri[tid][0];
#pragma unroll
        for (int t = 1; t < 16; t++) {
            float v = sm.r.Rv[tid][t];
            int  ix = sm.r.Ri[tid][t];
            if (v < bv || (v == bv && ix < bi)) { bv = v; bi = ix; }
        }
        g_idx[n0 + tid] = bi;
    }
}

// ---------------------------------------------------------------------------
// Kernel 2: quantized_st = x + (q - x) in [B,C,H,W] layout + loss partials.
// Smem-staged gather: coalesced float4 reads of w rows, XOR-swizzled store,
// conflict-free transposed read-out, coalesced x reads / out writes.
// grid = 1024 (b * 32 hw-chunks), block = 256.
__global__ __launch_bounds__(256) void k_quant(const float* __restrict__ x,
                                               const float* __restrict__ w,
                                               float* __restrict__ outq) {
    __shared__ float4 Qs[32][64];   // [row][slot ^ row]
    __shared__ int sidx[32];
    __shared__ float sred[8];
    const int t = threadIdx.x;
    const int b = blockIdx.x >> 5;
    const int hw0 = (blockIdx.x & 31) << 5;
    if (t < 32) sidx[t] = g_idx[(b << 10) + hw0 + t];
    __syncthreads();

    // load phase: 32 codebook rows, coalesced float4
    const int r0 = t >> 6;        // 0..3
    const int c4 = t & 63;
#pragma unroll
    for (int j = 0; j < 8; ++j) {
        const int r = r0 + (j << 2);
        const float4* wr = (const float4*)(w + sidx[r] * D);
        Qs[r][c4 ^ r] = wr[c4];
    }
    __syncthreads();

    // write phase: thread (c = hw lane, s0 = slot group)
    const int c = t & 31;
    const int s0 = t >> 5;        // 0..7
    const float* xb = x + b * (D * HW) + hw0 + c;
    float*       ob = outq + b * (D * HW) + hw0 + c;
    float accv = 0.f;
#pragma unroll
    for (int j = 0; j < 8; ++j) {
        const int s = s0 + (j << 3);     // slot 0..63 -> d = 4s
        float4 q = Qs[c][s ^ c];
        const int d = s << 2;
        float qq[4] = {q.x, q.y, q.z, q.w};
#pragma unroll
        for (int k2 = 0; k2 < 4; ++k2) {
            float xv = xb[(d + k2) * HW];
            float df = qq[k2] - xv;
            ob[(d + k2) * HW] = xv + df;   // straight-through value
            accv += df * df;
        }
    }
    float v = block_reduce_f(accv, sred);
    if (t == 0) g_partial[blockIdx.x] = v;
}

// ---------------------------------------------------------------------------
// Kernel 3: one-hot encodings (float2; base 8B aligned) + exact int histogram.
__global__ __launch_bounds__(256) void k_enc(float2* __restrict__ enc) {
    unsigned gid = blockIdx.x * 256u + threadIdx.x;  // < N*K/2
    int n  = gid >> 9;
    int c2 = gid & 511;
    int idx = __ldg(&g_idx[n]);
    float2 v = make_float2(0.f, 0.f);
    if ((idx >> 1) == c2) {
        if (idx & 1) v.y = 1.f; else v.x = 1.f;
        atomicAdd(&g_hist[idx], 1);
    }
    enc[gid] = v;
}

// ---------------------------------------------------------------------------
// Kernel 4: finalize loss + perplexity (deterministic double reductions).
__global__ __launch_bounds__(256) void k_final(float* __restrict__ out) {
    __shared__ double sd[8];
    int tid = threadIdx.x;

    double s = 0.0;
    for (int i = tid; i < NPART; i += 256) s += (double)g_partial[i];
#pragma unroll
    for (int o = 16; o; o >>= 1) s += __shfl_down_sync(0xffffffffu, s, o);
    if ((tid & 31) == 0) sd[tid >> 5] = s;
    __syncthreads();
    if (tid == 0) {
        double t = 0.0;
        for (int i = 0; i < 8; i++) t += sd[i];
        out[0] = (float)(t / (double)QELEMS * 1.25);
    }
    __syncthreads();

    double e = 0.0;
    for (int i = tid; i < K; i += 256) {
        double p = (double)g_hist[i] / (double)N;
        e += p * log(p + 1e-10);
    }
#pragma unroll
    for (int o = 16; o; o >>= 1) e += __shfl_down_sync(0xffffffffu, e, o);
    if ((tid & 31) == 0) sd[tid >> 5] = e;
    __syncthreads();
    if (tid == 0) {
        double t = 0.0;
        for (int i = 0; i < 8; i++) t += sd[i];
        out[1 + QELEMS] = (float)exp(-t);
    }
}

// ---------------------------------------------------------------------------
extern "C" void kernel_launch(void* const* d_in, const int* in_sizes, int n_in,
                              void* d_out, int out_size) {
    const float* x = (const float*)d_in[0];   // inputs [32,256,32,32]
    const float* w = (const float*)d_in[1];   // weight [1024,256]
    float* out = (float*)d_out;
    // Output layout: [0]=loss, [1 .. 1+QELEMS)=quantized_st,
    //                [1+QELEMS]=perplexity, [2+QELEMS .. )=encodings
    k_wnorm <<<K, 256>>>(w);
    k_xnorm <<<N / 32, dim3(32, 8)>>>(x);
    k_argmin<<<N / BM, 256>>>(x, w);
    k_quant <<<NPART, 256>>>(x, w, out + 1);
    k_enc   <<<(N * (K / 2)) / 256, 256>>>((float2*)(out + 2 + QELEMS));
    k_final <<<1, 256>>>(out);
}